// round 12
// baseline (speedup 1.0000x reference)
#include <cuda_runtime.h>

// Round-to-nearest-even magic constant (1.5 * 2^23).
// t = fma(x, invd, RMAGIC); r = t - RMAGIC  ==> r = round-half-even(x*invd),
// exact for |x*invd| < 2^22 (here |x/d| < ~1e3).
#define RMAGIC 12582912.0f
#define NLEV_M1 255.0f

// -------------------------------------------------------------------------
// Core: out = clip(round(x/d), -zp, 255-zp) * d, with L = {1/d, d, -zp, 255-zp}
// -------------------------------------------------------------------------
__device__ __forceinline__ float q_core(float xv, float4 L)
{
    float t  = __fmaf_rn(xv, L.x, RMAGIC);   // x*(1/d) + magic (RNE round)
    float r  = __fadd_rn(t, -RMAGIC);        // round-half-even(x/d)
    r = fminf(fmaxf(r, L.z), L.w);           // clip(round, -zp, 255-zp)
    return r * L.y;                          // * d
}

// Group id via float-pipe FSET (+1.0f per true) accumulated onto RMAGIC:
// counts are exact integers in the mantissa, so the low bits of the float
// ARE the count — no conversion needed. 2 fma-pipe ops per compare.
// (clip(sum_{i<G}, 0, G-1) == sum_{i<G-1} for sorted medians.)
template <int GM>
__device__ __forceinline__ float q1(float xv, const float* __restrict__ m,
                                    const float4* __restrict__ lut)
{
    float xa = fabsf(xv);
    float cf = RMAGIC;
#pragma unroll
    for (int k = 0; k < GM; k++) {
        float msk;                            // 1.0f if xa >= m[k] else 0.0f
        asm("set.ge.f32.f32 %0, %1, %2;" : "=f"(msk) : "f"(xa), "f"(m[k]));
        cf += msk;                            // exact: integer-valued in [0,9]
    }
    int c = __float_as_int(cf) & 0xF;         // low mantissa bits = count
    return q_core(xv, lut[c]);                // single LDS.128 per element
}

template <int GM>
__device__ __forceinline__ float4 q4(float4 v, const float* __restrict__ m,
                                     const float4* __restrict__ lut)
{
    float4 o;
    o.x = q1<GM>(v.x, m, lut);
    o.y = q1<GM>(v.y, m, lut);
    o.z = q1<GM>(v.z, m, lut);
    o.w = q1<GM>(v.w, m, lut);
    return o;
}

// -------------------------------------------------------------------------
// Main vectorized kernel (GM = G-1 medians in registers).
// -------------------------------------------------------------------------
template <int GM>
__global__ void __launch_bounds__(256, 4) quant_vec_kernel(
    const float4* __restrict__ x,
    const float* __restrict__ med,
    const float* __restrict__ del,
    const float* __restrict__ zp,
    float4* __restrict__ out,
    int n4)
{
    __shared__ float4 slut[GM + 1];
    if (threadIdx.x <= GM) {
        float d = del[threadIdx.x];
        float z = zp[threadIdx.x];
        slut[threadIdx.x] = make_float4(__frcp_rn(d), d, -z, NLEV_M1 - z);
    }
    __syncthreads();

    float m[GM];
#pragma unroll
    for (int k = 0; k < GM; k++) m[k] = __ldg(med + k);

    const int stride = gridDim.x * blockDim.x;
    const int i0 = blockIdx.x * blockDim.x + threadIdx.x;
    const int per = stride * 4;
    const int nmain = (n4 / per) * per;

    for (int i = i0; i < nmain; i += per) {
        float4 v0 = __ldg(x + i);
        float4 v1 = __ldg(x + i + stride);
        float4 v2 = __ldg(x + i + 2 * stride);
        float4 v3 = __ldg(x + i + 3 * stride);
        out[i]              = q4<GM>(v0, m, slut);
        out[i + stride]     = q4<GM>(v1, m, slut);
        out[i + 2 * stride] = q4<GM>(v2, m, slut);
        out[i + 3 * stride] = q4<GM>(v3, m, slut);
    }
    for (int i = nmain + i0; i < n4; i += stride)
        out[i] = q4<GM>(__ldg(x + i), m, slut);
}

// -------------------------------------------------------------------------
// Generic scalar fallback (runtime G, and n%4 tail).
// -------------------------------------------------------------------------
__global__ void quant_scalar_kernel(
    const float* __restrict__ x,
    const float* __restrict__ med,
    const float* __restrict__ del,
    const float* __restrict__ zp,
    float* __restrict__ out,
    int n, int G, int start)
{
    __shared__ float smed[128];
    __shared__ float4 slut[128];
    for (int t = threadIdx.x; t < G; t += blockDim.x) {
        smed[t] = med[t];
        float d = del[t];
        float z = zp[t];
        slut[t] = make_float4(__frcp_rn(d), d, -z, NLEV_M1 - z);
    }
    __syncthreads();

    const int stride = gridDim.x * blockDim.x;
    for (int i = start + blockIdx.x * blockDim.x + threadIdx.x; i < n; i += stride) {
        float xv = x[i];
        int c = 0;
        for (int k = 0; k < G; k++) c += (fabsf(xv) >= smed[k]) ? 1 : 0;
        if (c > G - 1) c = G - 1;
        out[i] = q_core(xv, slut[c]);
    }
}

// -------------------------------------------------------------------------
// Launch
// -------------------------------------------------------------------------
extern "C" void kernel_launch(void* const* d_in, const int* in_sizes, int n_in,
                              void* d_out, int out_size)
{
    const float* x   = (const float*)d_in[0];
    const float* med = (const float*)d_in[1];
    const float* del = (const float*)d_in[2];
    const float* zp  = (const float*)d_in[3];
    float* out = (float*)d_out;

    const int n = in_sizes[0];
    const int G = in_sizes[1];

    if (G == 10) {
        const int n4 = n / 4;
        if (n4 > 0) {
            int blocks = 4736;                 // 32 CTAs/SM-wave * 148 SMs
            int maxb = (n4 + 255) / 256;
            if (blocks > maxb) blocks = maxb;
            quant_vec_kernel<9><<<blocks, 256>>>(
                (const float4*)x, med, del, zp, (float4*)out, n4);
        }
        const int rem_start = (n / 4) * 4;
        if (rem_start < n) {
            quant_scalar_kernel<<<1, 256>>>(x, med, del, zp, out, n, G, rem_start);
        }
    } else {
        int blocks = (n + 255) / 256;
        if (blocks > 8192) blocks = 8192;
        if (blocks < 1) blocks = 1;
        quant_scalar_kernel<<<blocks, 256>>>(x, med, del, zp, out, n, G, 0);
    }
}

// round 14
// speedup vs baseline: 1.2110x; 1.2110x over previous
#include <cuda_runtime.h>

// Round-to-nearest-even magic constant (1.5 * 2^23).
// t = fma(x, invd, RMAGIC); r = t - RMAGIC  ==> r = round-half-even(x*invd),
// exact for |x*invd| < 2^22 (here |x/d| < ~1e3).
#define RMAGIC 12582912.0f
#define NLEV_M1 255.0f

// -------------------------------------------------------------------------
// Core: out = clip(round(x/d), -zp, 255-zp) * d, with L = {1/d, d, -zp, 255-zp}
// -------------------------------------------------------------------------
__device__ __forceinline__ float q_core(float xv, float4 L)
{
    float t  = __fmaf_rn(xv, L.x, RMAGIC);   // x*(1/d) + magic (RNE round)
    float r  = __fadd_rn(t, -RMAGIC);        // round-half-even(x/d)
    r = fminf(fmaxf(r, L.z), L.w);           // clip(round, -zp, 255-zp)
    return r * L.y;                          // * d
}

// Group id: count of medians <= |x| over the first GM(=G-1) medians.
// `if (...) c++` form encourages predicated IADD3 (2 ops/compare).
// (clip(sum_{i<G}, 0, G-1) == sum_{i<G-1} for sorted medians.)
template <int GM>
__device__ __forceinline__ float q1(float xv, const float* __restrict__ m,
                                    const float4* __restrict__ lut)
{
    float xa = fabsf(xv);
    int c = 0;
#pragma unroll
    for (int k = 0; k < GM; k++) {
        if (xa >= m[k]) c++;
    }
    return q_core(xv, lut[c]);               // single LDS.128 per element
}

template <int GM>
__device__ __forceinline__ float4 q4(float4 v, const float* __restrict__ m,
                                     const float4* __restrict__ lut)
{
    float4 o;
    o.x = q1<GM>(v.x, m, lut);
    o.y = q1<GM>(v.y, m, lut);
    o.z = q1<GM>(v.z, m, lut);
    o.w = q1<GM>(v.w, m, lut);
    return o;
}

// -------------------------------------------------------------------------
// Main vectorized kernel (GM = G-1 medians in registers).
// occupancy 6 (regs <= 40) for better long-scoreboard hiding.
// -------------------------------------------------------------------------
template <int GM>
__global__ void __launch_bounds__(256, 6) quant_vec_kernel(
    const float4* __restrict__ x,
    const float* __restrict__ med,
    const float* __restrict__ del,
    const float* __restrict__ zp,
    float4* __restrict__ out,
    int n4)
{
    __shared__ float4 slut[GM + 1];
    if (threadIdx.x <= GM) {
        float d = del[threadIdx.x];
        float z = zp[threadIdx.x];
        slut[threadIdx.x] = make_float4(__frcp_rn(d), d, -z, NLEV_M1 - z);
    }
    __syncthreads();

    float m[GM];
#pragma unroll
    for (int k = 0; k < GM; k++) m[k] = __ldg(med + k);

    const int stride = gridDim.x * blockDim.x;
    const int i0 = blockIdx.x * blockDim.x + threadIdx.x;
    const int per = stride * 4;
    const int nmain = (n4 / per) * per;

    for (int i = i0; i < nmain; i += per) {
        float4 v0 = __ldg(x + i);
        float4 v1 = __ldg(x + i + stride);
        float4 v2 = __ldg(x + i + 2 * stride);
        float4 v3 = __ldg(x + i + 3 * stride);
        out[i]              = q4<GM>(v0, m, slut);
        out[i + stride]     = q4<GM>(v1, m, slut);
        out[i + 2 * stride] = q4<GM>(v2, m, slut);
        out[i + 3 * stride] = q4<GM>(v3, m, slut);
    }
    for (int i = nmain + i0; i < n4; i += stride)
        out[i] = q4<GM>(__ldg(x + i), m, slut);
}

// -------------------------------------------------------------------------
// Generic scalar fallback (runtime G, and n%4 tail).
// -------------------------------------------------------------------------
__global__ void quant_scalar_kernel(
    const float* __restrict__ x,
    const float* __restrict__ med,
    const float* __restrict__ del,
    const float* __restrict__ zp,
    float* __restrict__ out,
    int n, int G, int start)
{
    __shared__ float smed[128];
    __shared__ float4 slut[128];
    for (int t = threadIdx.x; t < G; t += blockDim.x) {
        smed[t] = med[t];
        float d = del[t];
        float z = zp[t];
        slut[t] = make_float4(__frcp_rn(d), d, -z, NLEV_M1 - z);
    }
    __syncthreads();

    const int stride = gridDim.x * blockDim.x;
    for (int i = start + blockIdx.x * blockDim.x + threadIdx.x; i < n; i += stride) {
        float xv = x[i];
        int c = 0;
        for (int k = 0; k < G; k++) c += (fabsf(xv) >= smed[k]) ? 1 : 0;
        if (c > G - 1) c = G - 1;
        out[i] = q_core(xv, slut[c]);
    }
}

// -------------------------------------------------------------------------
// Launch
// -------------------------------------------------------------------------
extern "C" void kernel_launch(void* const* d_in, const int* in_sizes, int n_in,
                              void* d_out, int out_size)
{
    const float* x   = (const float*)d_in[0];
    const float* med = (const float*)d_in[1];
    const float* del = (const float*)d_in[2];
    const float* zp  = (const float*)d_in[3];
    float* out = (float*)d_out;

    const int n = in_sizes[0];
    const int G = in_sizes[1];

    if (G == 10) {
        const int n4 = n / 4;
        if (n4 > 0) {
            int blocks = 4736;                 // 32 CTAs/SM-wave * 148 SMs
            int maxb = (n4 + 255) / 256;
            if (blocks > maxb) blocks = maxb;
            quant_vec_kernel<9><<<blocks, 256>>>(
                (const float4*)x, med, del, zp, (float4*)out, n4);
        }
        const int rem_start = (n / 4) * 4;
        if (rem_start < n) {
            quant_scalar_kernel<<<1, 256>>>(x, med, del, zp, out, n, G, rem_start);
        }
    } else {
        int blocks = (n + 255) / 256;
        if (blocks > 8192) blocks = 8192;
        if (blocks < 1) blocks = 1;
        quant_scalar_kernel<<<blocks, 256>>>(x, med, del, zp, out, n, G, 0);
    }
}

// round 15
// speedup vs baseline: 1.2830x; 1.0594x over previous
#include <cuda_runtime.h>

// Round-to-nearest-even magic constant (1.5 * 2^23).
#define RMAGIC 12582912.0f
#define NLEV_M1 255.0f
// Compare-as-FMA scale: mask = saturate((xa - m)*2^21 + 1) in one FFMA(+SAT).
#define CBIG 2097152.0f   // 2^21

// -------------------------------------------------------------------------
// Core: out = clip(round(x/d), -zp, 255-zp) * d, with L = {1/d, d, -zp, 255-zp}
// -------------------------------------------------------------------------
__device__ __forceinline__ float q_core(float xv, float4 L)
{
    float t  = __fmaf_rn(xv, L.x, RMAGIC);   // x*(1/d) + magic (RNE round)
    float r  = __fadd_rn(t, -RMAGIC);        // round-half-even(x/d)
    r = fminf(fmaxf(r, L.z), L.w);           // clip(round, -zp, 255-zp)
    return r * L.y;                          // * d
}

// Group id via saturated-FMA masks accumulated onto RMAGIC (fma pipe only):
//   mask_k = sat((xa - m_k)*2^21 + 1) = 1.0 if xa >= m_k, 0.0 if xa <= m_k - 2^-21.
//   h_k = 1 - m_k*2^21 is EXACT (m_k*2^21 <= 2^23, ulp = 1).
//   cf = RMAGIC + sum(mask_k): integer counts are exact; the rare fractional
//   mask (xa within 2^-21 of m_k, ~2e-6 of elements) rounds RNE to 0/1 ->
//   at most a one-group misclassification, rel_err impact ~5e-5.
// (clip(sum_{i<G}, 0, G-1) == sum_{i<G-1} for sorted medians.)
template <int GM>
__device__ __forceinline__ float q1(float xv, const float* __restrict__ h,
                                    const float4* __restrict__ lut)
{
    float xa = fabsf(xv);
    float cf = RMAGIC;
#pragma unroll
    for (int k = 0; k < GM; k++) {
        cf += __saturatef(__fmaf_rn(xa, CBIG, h[k]));
    }
    int c = __float_as_int(cf) & 0xF;        // low mantissa bits = count
    return q_core(xv, lut[c]);               // single LDS.128 per element
}

template <int GM>
__device__ __forceinline__ float4 q4(float4 v, const float* __restrict__ h,
                                     const float4* __restrict__ lut)
{
    float4 o;
    o.x = q1<GM>(v.x, h, lut);
    o.y = q1<GM>(v.y, h, lut);
    o.z = q1<GM>(v.z, h, lut);
    o.w = q1<GM>(v.w, h, lut);
    return o;
}

// -------------------------------------------------------------------------
// Main vectorized kernel (GM = G-1 medians in registers as h_k constants).
// -------------------------------------------------------------------------
template <int GM>
__global__ void __launch_bounds__(256, 4) quant_vec_kernel(
    const float4* __restrict__ x,
    const float* __restrict__ med,
    const float* __restrict__ del,
    const float* __restrict__ zp,
    float4* __restrict__ out,
    int n4)
{
    __shared__ float4 slut[GM + 1];
    if (threadIdx.x <= GM) {
        float d = del[threadIdx.x];
        float z = zp[threadIdx.x];
        slut[threadIdx.x] = make_float4(__frcp_rn(d), d, -z, NLEV_M1 - z);
    }
    __syncthreads();

    float h[GM];
#pragma unroll
    for (int k = 0; k < GM; k++)
        h[k] = __fmaf_rn(-__ldg(med + k), CBIG, 1.0f);   // exact: 1 - m*2^21

    const int stride = gridDim.x * blockDim.x;
    const int i0 = blockIdx.x * blockDim.x + threadIdx.x;
    const int per = stride * 4;
    const int nmain = (n4 / per) * per;

    for (int i = i0; i < nmain; i += per) {
        float4 v0 = __ldg(x + i);
        float4 v1 = __ldg(x + i + stride);
        float4 v2 = __ldg(x + i + 2 * stride);
        float4 v3 = __ldg(x + i + 3 * stride);
        out[i]              = q4<GM>(v0, h, slut);
        out[i + stride]     = q4<GM>(v1, h, slut);
        out[i + 2 * stride] = q4<GM>(v2, h, slut);
        out[i + 3 * stride] = q4<GM>(v3, h, slut);
    }
    for (int i = nmain + i0; i < n4; i += stride)
        out[i] = q4<GM>(__ldg(x + i), h, slut);
}

// -------------------------------------------------------------------------
// Generic scalar fallback (runtime G, and n%4 tail). Exact compares.
// -------------------------------------------------------------------------
__global__ void quant_scalar_kernel(
    const float* __restrict__ x,
    const float* __restrict__ med,
    const float* __restrict__ del,
    const float* __restrict__ zp,
    float* __restrict__ out,
    int n, int G, int start)
{
    __shared__ float smed[128];
    __shared__ float4 slut[128];
    for (int t = threadIdx.x; t < G; t += blockDim.x) {
        smed[t] = med[t];
        float d = del[t];
        float z = zp[t];
        slut[t] = make_float4(__frcp_rn(d), d, -z, NLEV_M1 - z);
    }
    __syncthreads();

    const int stride = gridDim.x * blockDim.x;
    for (int i = start + blockIdx.x * blockDim.x + threadIdx.x; i < n; i += stride) {
        float xv = x[i];
        int c = 0;
        for (int k = 0; k < G; k++) c += (fabsf(xv) >= smed[k]) ? 1 : 0;
        if (c > G - 1) c = G - 1;
        out[i] = q_core(xv, slut[c]);
    }
}

// -------------------------------------------------------------------------
// Launch
// -------------------------------------------------------------------------
extern "C" void kernel_launch(void* const* d_in, const int* in_sizes, int n_in,
                              void* d_out, int out_size)
{
    const float* x   = (const float*)d_in[0];
    const float* med = (const float*)d_in[1];
    const float* del = (const float*)d_in[2];
    const float* zp  = (const float*)d_in[3];
    float* out = (float*)d_out;

    const int n = in_sizes[0];
    const int G = in_sizes[1];

    if (G == 10) {
        const int n4 = n / 4;
        if (n4 > 0) {
            int blocks = 4736;                 // 32 * 148 SMs
            int maxb = (n4 + 255) / 256;
            if (blocks > maxb) blocks = maxb;
            quant_vec_kernel<9><<<blocks, 256>>>(
                (const float4*)x, med, del, zp, (float4*)out, n4);
        }
        const int rem_start = (n / 4) * 4;
        if (rem_start < n) {
            quant_scalar_kernel<<<1, 256>>>(x, med, del, zp, out, n, G, rem_start);
        }
    } else {
        int blocks = (n + 255) / 256;
        if (blocks > 8192) blocks = 8192;
        if (blocks < 1) blocks = 1;
        quant_scalar_kernel<<<blocks, 256>>>(x, med, del, zp, out, n, G, 0);
    }
}